// round 1
// baseline (speedup 1.0000x reference)
#include <cuda_runtime.h>
#include <math.h>

#define NMAX 200000
#define EMAX 600000
#define HIDC 128
#define NH 8
#define HD 16

// ---------------- scratch (device globals; no runtime allocation) ----------------
__device__ float g_xA[2][(size_t)NMAX * HIDC];
__device__ float g_xB[2][(size_t)NMAX * HIDC];
__device__ float g_qb[2][(size_t)NMAX * HIDC];
__device__ float g_kr[2][(size_t)NMAX * HIDC];
__device__ float g_vr[2][(size_t)NMAX * HIDC];
__device__ float g_att[2][(size_t)NMAX * HIDC];
__device__ unsigned g_m[2][(size_t)NMAX * NH];
__device__ float g_s[2][(size_t)NMAX * NH];
__device__ float g_sc[2][(size_t)EMAX * NH];

// order-preserving float<->uint for atomicMax on floats
__device__ __forceinline__ unsigned fenc(float f) {
    unsigned u = __float_as_uint(f);
    return (u & 0x80000000u) ? ~u : (u | 0x80000000u);
}
__device__ __forceinline__ float fdec(unsigned u) {
    return __uint_as_float((u & 0x80000000u) ? (u & 0x7fffffffu) : ~u);
}
__device__ __forceinline__ float gelu_f(float x) {
    return 0.5f * x * (1.0f + erff(x * 0.7071067811865475f));
}

// ---------------- GEMM: C = epilogue( act_in(A) @ W + bias ) ----------------
// MODE: 0 plain, 1 relu, 2 per-head mix with Ahead[8][16][16], 3 skip-blend with x_old
// PRE_GELU: apply exact gelu to A elements while loading
template <int K, int NC, int MODE, int PRE_GELU>
__global__ void __launch_bounds__(256)
gemm_kernel(const float* __restrict__ A, const float* __restrict__ W,
            const float* __restrict__ bias, float* __restrict__ C, int nrows,
            const float* __restrict__ Ahead, const float* __restrict__ xold,
            const float* __restrict__ skipp)
{
    constexpr int TN = NC / 16;
    __shared__ float As[128][33];
    __shared__ float Bs[32][NC + 4];
    __shared__ float Ahs[(MODE == 2) ? (NH * HD * HD) : 1];

    const int tx = threadIdx.x & 15;
    const int ty = threadIdx.x >> 4;
    const int blockRow = blockIdx.x * 128;

    if (MODE == 2) {
        for (int i = threadIdx.x; i < NH * HD * HD; i += 256) Ahs[i] = Ahead[i];
    }

    float acc[8][TN];
#pragma unroll
    for (int i = 0; i < 8; ++i)
#pragma unroll
        for (int j = 0; j < TN; ++j) acc[i][j] = 0.f;

    for (int kt = 0; kt < K / 32; ++kt) {
        // load A tile 128x32 (row-major A[nrows][K])
#pragma unroll
        for (int p = 0; p < 4; ++p) {
            int t4 = threadIdx.x + p * 256;
            int r = t4 >> 3, c4 = t4 & 7;
            int grow = blockRow + r;
            float4 v = make_float4(0.f, 0.f, 0.f, 0.f);
            if (grow < nrows)
                v = *reinterpret_cast<const float4*>(A + (size_t)grow * K + kt * 32 + c4 * 4);
            if (PRE_GELU) {
                v.x = gelu_f(v.x); v.y = gelu_f(v.y); v.z = gelu_f(v.z); v.w = gelu_f(v.w);
            }
            As[r][c4 * 4 + 0] = v.x;
            As[r][c4 * 4 + 1] = v.y;
            As[r][c4 * 4 + 2] = v.z;
            As[r][c4 * 4 + 3] = v.w;
        }
        // load W tile 32xNC (row-major W[K][NC])
#pragma unroll
        for (int t4 = threadIdx.x; t4 < 32 * NC / 4; t4 += 256) {
            int kk = t4 / (NC / 4), c4 = t4 % (NC / 4);
            float4 v = *reinterpret_cast<const float4*>(W + (size_t)(kt * 32 + kk) * NC + c4 * 4);
            Bs[kk][c4 * 4 + 0] = v.x;
            Bs[kk][c4 * 4 + 1] = v.y;
            Bs[kk][c4 * 4 + 2] = v.z;
            Bs[kk][c4 * 4 + 3] = v.w;
        }
        __syncthreads();
#pragma unroll
        for (int kk = 0; kk < 32; ++kk) {
            float a[8];
#pragma unroll
            for (int i = 0; i < 8; ++i) a[i] = As[ty * 8 + i][kk];
            float b[TN];
#pragma unroll
            for (int j = 0; j < TN; j += 4) {
                float4 bv = *reinterpret_cast<const float4*>(&Bs[kk][tx * TN + j]);
                b[j] = bv.x; b[j + 1] = bv.y; b[j + 2] = bv.z; b[j + 3] = bv.w;
            }
#pragma unroll
            for (int i = 0; i < 8; ++i)
#pragma unroll
                for (int j = 0; j < TN; ++j) acc[i][j] = fmaf(a[i], b[j], acc[i][j]);
        }
        __syncthreads();
    }

    const int col0 = tx * TN;
    float bv[TN];
#pragma unroll
    for (int j = 0; j < TN; ++j) bv[j] = bias[col0 + j];

    float alpha = 0.f;
    if (MODE == 3) alpha = 1.f / (1.f + __expf(-skipp[0]));

#pragma unroll
    for (int i = 0; i < 8; ++i) {
        int grow = blockRow + ty * 8 + i;
        if (MODE == 2) {
            // per-head transform: out[n,h,e] = sum_d y[n,h*16+d] * Ahead[h,d,e]
            // thread owns 8 cols = half of head h=tx/2; partner lane (xor 1) has other half
            float y[8], oth[8];
#pragma unroll
            for (int j = 0; j < 8; ++j) y[j] = acc[i][j] + bv[j];
#pragma unroll
            for (int j = 0; j < 8; ++j) oth[j] = __shfl_xor_sync(0xffffffffu, y[j], 1);
            float yf[16];
            const bool hi = (tx & 1);
#pragma unroll
            for (int d = 0; d < 8; ++d) {
                yf[d]     = hi ? oth[d] : y[d];
                yf[8 + d] = hi ? y[d]   : oth[d];
            }
            const int h = tx >> 1;
            const int e0 = hi ? 8 : 0;
            float o[8];
#pragma unroll
            for (int j = 0; j < 8; ++j) {
                float s = 0.f;
#pragma unroll
                for (int d = 0; d < 16; ++d)
                    s = fmaf(yf[d], Ahs[(h * HD + d) * HD + e0 + j], s);
                o[j] = s;
            }
            if (grow < nrows) {
                float4* cp = reinterpret_cast<float4*>(C + (size_t)grow * NC + col0);
                cp[0] = make_float4(o[0], o[1], o[2], o[3]);
                cp[1] = make_float4(o[4], o[5], o[6], o[7]);
            }
        } else {
            if (grow >= nrows) continue;
            float o[TN];
#pragma unroll
            for (int j = 0; j < TN; ++j) {
                float v = acc[i][j] + bv[j];
                if (MODE == 1) v = fmaxf(v, 0.f);
                o[j] = v;
            }
            if (MODE == 3) {
#pragma unroll
                for (int j = 0; j < TN; ++j) {
                    float xo = xold[(size_t)grow * NC + col0 + j];
                    o[j] = alpha * o[j] + (1.f - alpha) * xo;
                }
            }
            float4* cp = reinterpret_cast<float4*>(C + (size_t)grow * NC + col0);
#pragma unroll
            for (int j = 0; j < TN; j += 4)
                cp[j / 4] = make_float4(o[j], o[j + 1], o[j + 2], o[j + 3]);
        }
    }
}

// ---------------- edge kernels ----------------
__global__ void init_ms_kernel(int n)
{
    int i = blockIdx.x * blockDim.x + threadIdx.x;
    if (i < n) {
        g_m[0][i] = 0x007FFFFFu;  // fenc(-inf)
        g_m[1][i] = 0x007FFFFFu;
        g_s[0][i] = 0.f;
        g_s[1][i] = 0.f;
    }
}

__global__ void edge_score_kernel(const int* __restrict__ src, const int* __restrict__ dst,
                                  const float* __restrict__ q, const float* __restrict__ kr,
                                  const float* __restrict__ prel, float* __restrict__ sc,
                                  unsigned* __restrict__ mmax, int E)
{
    int idx = blockIdx.x * blockDim.x + threadIdx.x;
    if (idx >= E * NH) return;
    int e = idx >> 3, h = idx & 7;
    int si = src[e], di = dst[e];
    const float4* qp = reinterpret_cast<const float4*>(q + (size_t)di * HIDC + h * HD);
    const float4* kp = reinterpret_cast<const float4*>(kr + (size_t)si * HIDC + h * HD);
    float s = 0.f;
#pragma unroll
    for (int t = 0; t < 4; ++t) {
        float4 a = qp[t], b = kp[t];
        s += a.x * b.x + a.y * b.y + a.z * b.z + a.w * b.w;
    }
    s *= prel[h] * 0.25f;  // * p_rel * 1/sqrt(D)
    sc[idx] = s;
    atomicMax(&mmax[(size_t)di * NH + h], fenc(s));
}

__global__ void edge_exp_kernel(const int* __restrict__ dst, float* __restrict__ sc,
                                const unsigned* __restrict__ mmax, float* __restrict__ ssum, int E)
{
    int idx = blockIdx.x * blockDim.x + threadIdx.x;
    if (idx >= E * NH) return;
    int e = idx >> 3, h = idx & 7;
    int di = dst[e];
    float m = fdec(mmax[(size_t)di * NH + h]);
    float ex = __expf(sc[idx] - m);
    sc[idx] = ex;
    atomicAdd(&ssum[(size_t)di * NH + h], ex);
}

__global__ void edge_scatter_kernel(const int* __restrict__ src, const int* __restrict__ dst,
                                    const float* __restrict__ vr, const float* __restrict__ sc,
                                    const float* __restrict__ ssum, float* __restrict__ out, int E)
{
    int idx = blockIdx.x * blockDim.x + threadIdx.x;
    if (idx >= E * NH) return;
    int e = idx >> 3, h = idx & 7;
    int si = src[e], di = dst[e];
    float a = sc[idx] / (ssum[(size_t)di * NH + h] + 1e-16f);
    const float4* vp = reinterpret_cast<const float4*>(vr + (size_t)si * HIDC + h * HD);
    float* op = out + (size_t)di * HIDC + h * HD;
#pragma unroll
    for (int t = 0; t < 4; ++t) {
        float4 v = vp[t];
        atomicAdd(op + t * 4 + 0, v.x * a);
        atomicAdd(op + t * 4 + 1, v.y * a);
        atomicAdd(op + t * 4 + 2, v.z * a);
        atomicAdd(op + t * 4 + 3, v.w * a);
    }
}

// ---------------- launch ----------------
extern "C" void kernel_launch(void* const* d_in, const int* in_sizes, int n_in,
                              void* d_out, int out_size)
{
    const float* x_cpd    = (const float*)d_in[0];
    const float* x_ko     = (const float*)d_in[1];
    const int*   e_c2k    = (const int*)d_in[2];
    const int*   e_k2c    = (const int*)d_in[3];
    const float* w_in_cpd = (const float*)d_in[4];
    const float* b_in_cpd = (const float*)d_in[5];
    const float* w_in_ko  = (const float*)d_in[6];
    const float* b_in_ko  = (const float*)d_in[7];

    const float *w_k, *b_k, *w_q, *b_q, *w_v, *b_v;
    const float *a_rel, *m_rel, *p_rel, *w_a, *b_a, *skip, *w_out, *b_out;
    if (in_sizes[9] == 2 * 2 * HIDC) {
        // signature order: w_k,b_k,w_q,b_q,w_v,b_v,a_rel,m_rel,p_rel,w_a,b_a,skip,w_out,b_out
        w_k = (const float*)d_in[8];   b_k = (const float*)d_in[9];
        w_q = (const float*)d_in[10];  b_q = (const float*)d_in[11];
        w_v = (const float*)d_in[12];  b_v = (const float*)d_in[13];
        a_rel = (const float*)d_in[14]; m_rel = (const float*)d_in[15];
        p_rel = (const float*)d_in[16];
        w_a = (const float*)d_in[17];  b_a = (const float*)d_in[18];
        skip = (const float*)d_in[19];
        w_out = (const float*)d_in[20]; b_out = (const float*)d_in[21];
    } else {
        // setup_inputs dict order: w_k,w_q,w_v,w_a,b_k,b_q,b_v,b_a,a_rel,m_rel,p_rel,skip,w_out,b_out
        w_k = (const float*)d_in[8];   w_q = (const float*)d_in[9];
        w_v = (const float*)d_in[10];  w_a = (const float*)d_in[11];
        b_k = (const float*)d_in[12];  b_q = (const float*)d_in[13];
        b_v = (const float*)d_in[14];  b_a = (const float*)d_in[15];
        a_rel = (const float*)d_in[16]; m_rel = (const float*)d_in[17];
        p_rel = (const float*)d_in[18]; skip = (const float*)d_in[19];
        w_out = (const float*)d_in[20]; b_out = (const float*)d_in[21];
    }

    const int N = in_sizes[0] / 64;
    const int E = in_sizes[2] / 2;

    void* p;
    float *xA, *xB, *qb, *kr, *vr, *att, *sb, *sc;
    unsigned* mb;
    cudaGetSymbolAddress(&p, g_xA);  xA  = (float*)p;
    cudaGetSymbolAddress(&p, g_xB);  xB  = (float*)p;
    cudaGetSymbolAddress(&p, g_qb);  qb  = (float*)p;
    cudaGetSymbolAddress(&p, g_kr);  kr  = (float*)p;
    cudaGetSymbolAddress(&p, g_vr);  vr  = (float*)p;
    cudaGetSymbolAddress(&p, g_att); att = (float*)p;
    cudaGetSymbolAddress(&p, g_m);   mb  = (unsigned*)p;
    cudaGetSymbolAddress(&p, g_s);   sb  = (float*)p;
    cudaGetSymbolAddress(&p, g_sc);  sc  = (float*)p;

    const size_t NSTR = (size_t)NMAX * HIDC;
    const size_t MSTR = (size_t)NMAX * NH;
    const size_t ESTR = (size_t)EMAX * NH;

    dim3 gB((N + 127) / 128);
    const int egrid = (E * NH + 255) / 256;
    const int igrid = (N * NH + 255) / 256;

    // input projections + relu
    gemm_kernel<64, 128, 1, 0><<<gB, 256>>>(x_cpd, w_in_cpd, b_in_cpd, xA + 0 * NSTR, N, nullptr, nullptr, nullptr);
    gemm_kernel<128, 128, 1, 0><<<gB, 256>>>(x_ko, w_in_ko, b_in_ko, xA + 1 * NSTR, N, nullptr, nullptr, nullptr);

    float* xcur = xA;
    float* xnxt = xB;

    for (int l = 0; l < 2; ++l) {
        for (int t = 0; t < 2; ++t) {
            size_t lt = (size_t)l * 2 + t;
            // q (type t as destination in relation 1-t)
            gemm_kernel<128, 128, 0, 0><<<gB, 256>>>(xcur + t * NSTR, w_q + lt * HIDC * HIDC, b_q + lt * HIDC,
                                                     qb + t * NSTR, N, nullptr, nullptr, nullptr);
            // kr = (x@w_k+b) per-head a_rel[l, r=t]  (type t is source of relation t)
            gemm_kernel<128, 128, 2, 0><<<gB, 256>>>(xcur + t * NSTR, w_k + lt * HIDC * HIDC, b_k + lt * HIDC,
                                                     kr + t * NSTR, N, a_rel + lt * NH * HD * HD, nullptr, nullptr);
            // vr with m_rel[l, r=t]
            gemm_kernel<128, 128, 2, 0><<<gB, 256>>>(xcur + t * NSTR, w_v + lt * HIDC * HIDC, b_v + lt * HIDC,
                                                     vr + t * NSTR, N, m_rel + lt * NH * HD * HD, nullptr, nullptr);
        }
        init_ms_kernel<<<igrid, 256>>>(N * NH);
        cudaMemsetAsync(att, 0, sizeof(float) * 2 * NSTR);
        for (int r = 0; r < 2; ++r) {
            const int* ep = (r == 0) ? e_c2k : e_k2c;
            int st = r, dt = 1 - r;
            size_t lr = (size_t)l * 2 + r;
            edge_score_kernel<<<egrid, 256>>>(ep, ep + E, qb + dt * NSTR, kr + st * NSTR,
                                              p_rel + lr * NH, sc + r * ESTR, mb + r * MSTR, E);
            edge_exp_kernel<<<egrid, 256>>>(ep + E, sc + r * ESTR, mb + r * MSTR, sb + r * MSTR, E);
            edge_scatter_kernel<<<egrid, 256>>>(ep, ep + E, vr + st * NSTR, sc + r * ESTR,
                                                sb + r * MSTR, att + dt * NSTR, E);
        }
        for (int t = 0; t < 2; ++t) {
            size_t lt = (size_t)l * 2 + t;
            // x_new = sigmoid(skip)*(gelu(att)@w_a + b_a) + (1-sigmoid(skip))*x
            gemm_kernel<128, 128, 3, 1><<<gB, 256>>>(att + t * NSTR, w_a + lt * HIDC * HIDC, b_a + lt * HIDC,
                                                     xnxt + t * NSTR, N, nullptr, xcur + t * NSTR, skip + lt);
        }
        float* tmp = xcur; xcur = xnxt; xnxt = tmp;
    }

    float* out = (float*)d_out;
    gemm_kernel<128, 64, 0, 0><<<gB, 256>>>(xcur + 0 * NSTR, w_out, b_out, out, N, nullptr, nullptr, nullptr);
    gemm_kernel<128, 64, 0, 0><<<gB, 256>>>(xcur + 1 * NSTR, w_out, b_out, out + (size_t)N * 64, N, nullptr, nullptr, nullptr);
}

// round 3
// speedup vs baseline: 1.8453x; 1.8453x over previous
#include <cuda_runtime.h>
#include <cuda_bf16.h>
#include <math.h>
#include <stdint.h>

#define NMAX 200000
#define EMAX 600000
#define HIDC 128
#define NH 8
#define HD 16

// A/B smem tile: 128 rows x 136 bf16 (272 bytes per row; +16B pad -> conflict-free ldmatrix)
#define ROWB 272
#define HALFB 34816        // 128 * 272
#define SM_AH 0
#define SM_AL 34816
#define SM_BH 69632
#define SM_BL 104448
#define SMEM_TOT 139264

// ---------------- scratch (device globals; no runtime allocation) ----------------
__device__ float g_xA[2][(size_t)NMAX * HIDC];
__device__ float g_xB[2][(size_t)NMAX * HIDC];
__device__ float g_qb[2][(size_t)NMAX * HIDC];
__device__ float g_kr[2][(size_t)NMAX * HIDC];
__device__ float g_vr[2][(size_t)NMAX * HIDC];
__device__ float g_att[2][(size_t)NMAX * HIDC];
__device__ unsigned g_m[2][(size_t)NMAX * NH];
__device__ float g_s[2][(size_t)NMAX * NH];
__device__ float g_sc[2][(size_t)EMAX * NH];
// prepped weights: 19 matrices, each 69632 B (hi image 34816 + lo image 34816), smem-ready
__device__ uint4 g_wblob[19][4352];
__device__ float g_biasP[19][128];

// ---------------- helpers ----------------
__device__ __forceinline__ uint32_t smem_u32(const void* p) {
    uint32_t a;
    asm("{ .reg .u64 t; cvta.to.shared.u64 t, %1; cvt.u32.u64 %0, t; }" : "=r"(a) : "l"(p));
    return a;
}

#define LDM4(r0, r1, r2, r3, addr) \
    asm volatile("ldmatrix.sync.aligned.m8n8.x4.shared.b16 {%0,%1,%2,%3}, [%4];" \
                 : "=r"(r0), "=r"(r1), "=r"(r2), "=r"(r3) : "r"(addr))

#define MMA16816(c, a, b) \
    asm volatile("mma.sync.aligned.m16n8k16.row.col.f32.bf16.bf16.f32 " \
                 "{%0,%1,%2,%3},{%4,%5,%6,%7},{%8,%9},{%0,%1,%2,%3};" \
                 : "+f"((c)[0]), "+f"((c)[1]), "+f"((c)[2]), "+f"((c)[3]) \
                 : "r"((a)[0]), "r"((a)[1]), "r"((a)[2]), "r"((a)[3]), \
                   "r"((b)[0]), "r"((b)[1]))

__device__ __forceinline__ unsigned fenc(float f) {
    unsigned u = __float_as_uint(f);
    return (u & 0x80000000u) ? ~u : (u | 0x80000000u);
}
__device__ __forceinline__ float fdec(unsigned u) {
    return __uint_as_float((u & 0x80000000u) ? (u & 0x7fffffffu) : ~u);
}
__device__ __forceinline__ float gelu_f(float x) {
    return 0.5f * x * (1.0f + erff(x * 0.7071067811865475f));
}

// ---------------- weight prep: compose rel/p-scale, transpose to [n][k], bf16 hi/lo split ----------------
struct PrepJob {
    const float* W;    // [kin x nout] row-major
    const float* b;    // [nout]
    const float* rel;  // [8,16,16] or null
    const float* psc;  // [8] or null (also multiplies 0.25 = 1/sqrt(D))
    int kin;
    int nout;
    uint4* blob;
    float* bias;
};
struct PrepArgs { PrepJob j[19]; };

__global__ void prep_kernel(PrepArgs pa) {
    __shared__ float rel_s[2048];
    __shared__ float bsrc[128];
    const PrepJob jb = pa.j[blockIdx.x];
    const int tid = threadIdx.x;
    const bool hasrel = (jb.rel != nullptr);
    if (hasrel)
        for (int i = tid; i < 2048; i += 256) rel_s[i] = jb.rel[i];
    for (int i = tid; i < 128; i += 256) bsrc[i] = (i < jb.nout) ? jb.b[i] : 0.f;
    __syncthreads();

    char* blob = (char*)jb.blob;
    for (int i = tid; i < 16384; i += 256) {
        int k = i >> 7;
        int n = i & 127;
        float v = 0.f;
        if (k < jb.kin && n < jb.nout) {
            if (hasrel) {
                int h = n >> 4, e = n & 15;
                const float* wrow = jb.W + (size_t)k * 128 + h * 16;
                const float* rr = rel_s + h * 256 + e;
                float s = 0.f;
#pragma unroll
                for (int d = 0; d < 16; ++d) s = fmaf(wrow[d], rr[d * 16], s);
                v = s;
            } else {
                v = jb.W[(size_t)k * jb.nout + n];
            }
            if (jb.psc) v *= jb.psc[n >> 4] * 0.25f;
        }
        __nv_bfloat16 hi = __float2bfloat16(v);
        __nv_bfloat16 lo = __float2bfloat16(v - __bfloat162float(hi));
        uint32_t off = (uint32_t)n * ROWB + (uint32_t)k * 2;  // B stored [n][k]
        *reinterpret_cast<__nv_bfloat16*>(blob + off) = hi;
        *reinterpret_cast<__nv_bfloat16*>(blob + HALFB + off) = lo;
    }
    if (tid < 128) {
        int n = tid;
        float bc;
        if (hasrel) {
            int h = n >> 4, e = n & 15;
            float s = 0.f;
#pragma unroll
            for (int d = 0; d < 16; ++d) s = fmaf(bsrc[h * 16 + d], rel_s[h * 256 + d * 16 + e], s);
            bc = s;
        } else {
            bc = bsrc[n];
        }
        if (jb.psc) bc *= jb.psc[n >> 4] * 0.25f;
        jb.bias[n] = bc;
    }
}

// ---------------- bf16x3 HMMA GEMM ----------------
// C[m] = epilogue( act_in(A[nrows x kin]) @ Wt[m] + bias[m] ), m = 0..nmat-1
// MODE: 0 plain, 1 relu, 3 pre-gelu on A + sigmoid-skip blend with xold
template <int MODE>
__global__ void __launch_bounds__(256, 1)
gemm_hmma(const float* __restrict__ A, int kin,
          const uint4* __restrict__ blob, const float* __restrict__ bias,
          int nmat, int nout,
          float* __restrict__ c0, float* __restrict__ c1, float* __restrict__ c2,
          int nrows, const float* __restrict__ xold, const float* __restrict__ skipp)
{
    extern __shared__ char smem[];
    const uint32_t sb = smem_u32(smem);
    const int tid = threadIdx.x;
    const int lane = tid & 31, wid = tid >> 5;
    const int wr0 = (wid & 3) * 32;   // warp row offset within 128
    const int wc0 = (wid >> 2) * 64;  // warp col offset within 128
    const int row0 = blockIdx.x * 128;

    // ---- load A tile 128 x 128 fp32 -> bf16 hi/lo into smem ----
#pragma unroll
    for (int it = 0; it < 8; ++it) {
        int gid = it * 256 + tid;
        int r = gid >> 4;
        int c8 = (gid & 15) * 8;
        float f[8];
        int grow = row0 + r;
        if (grow < nrows && c8 < kin) {
            const float4* p = reinterpret_cast<const float4*>(A + (size_t)grow * kin + c8);
            float4 v0 = p[0], v1 = p[1];
            f[0] = v0.x; f[1] = v0.y; f[2] = v0.z; f[3] = v0.w;
            f[4] = v1.x; f[5] = v1.y; f[6] = v1.z; f[7] = v1.w;
        } else {
#pragma unroll
            for (int j = 0; j < 8; ++j) f[j] = 0.f;
        }
        if (MODE == 3) {
#pragma unroll
            for (int j = 0; j < 8; ++j) f[j] = gelu_f(f[j]);
        }
        uint32_t hw[4], lw[4];
#pragma unroll
        for (int j = 0; j < 4; ++j) {
            __nv_bfloat16 h0 = __float2bfloat16(f[2 * j]);
            __nv_bfloat16 h1 = __float2bfloat16(f[2 * j + 1]);
            __nv_bfloat16 l0 = __float2bfloat16(f[2 * j] - __bfloat162float(h0));
            __nv_bfloat16 l1 = __float2bfloat16(f[2 * j + 1] - __bfloat162float(h1));
            hw[j] = (uint32_t)__bfloat16_as_ushort(h0) | ((uint32_t)__bfloat16_as_ushort(h1) << 16);
            lw[j] = (uint32_t)__bfloat16_as_ushort(l0) | ((uint32_t)__bfloat16_as_ushort(l1) << 16);
        }
        uint32_t off = (uint32_t)r * ROWB + (uint32_t)c8 * 2;
        *reinterpret_cast<uint4*>(smem + SM_AH + off) = make_uint4(hw[0], hw[1], hw[2], hw[3]);
        *reinterpret_cast<uint4*>(smem + SM_AL + off) = make_uint4(lw[0], lw[1], lw[2], lw[3]);
    }
    __syncthreads();

    float alpha = 0.f;
    if (MODE == 3) alpha = 1.f / (1.f + __expf(-skipp[0]));

    // fragment addresses (lane-dependent, k-step added in loop)
    const uint32_t aAddrBase = sb + SM_AH + (uint32_t)(wr0 + (lane & 15)) * ROWB + (uint32_t)(lane >> 4) * 16;
    const uint32_t bRowN = (uint32_t)(wc0 + (lane & 7) + ((lane >> 4) & 1) * 8);
    const uint32_t bColK = (uint32_t)(((lane >> 3) & 1) * 8);
    const uint32_t bAddrBase = sb + SM_BH + bRowN * ROWB + bColK * 2;

    for (int m = 0; m < nmat; ++m) {
        if (m) __syncthreads();
        // copy prepped B images (hi 34816 + lo 34816, contiguous)
        const uint4* src = blob + (size_t)m * 4352;
        for (int i = tid; i < 4352; i += 256)
            *reinterpret_cast<uint4*>(smem + SM_BH + i * 16) = src[i];
        __syncthreads();

        float acc[2][8][4];
#pragma unroll
        for (int i = 0; i < 2; ++i)
#pragma unroll
            for (int j = 0; j < 8; ++j)
#pragma unroll
                for (int t = 0; t < 4; ++t) acc[i][j][t] = 0.f;

#pragma unroll 1
        for (int ks = 0; ks < 8; ++ks) {
            uint32_t ahi[2][4], alo[2][4];
#pragma unroll
            for (int i = 0; i < 2; ++i) {
                uint32_t ra = aAddrBase + (uint32_t)i * 16 * ROWB + (uint32_t)ks * 32;
                LDM4(ahi[i][0], ahi[i][1], ahi[i][2], ahi[i][3], ra);
                LDM4(alo[i][0], alo[i][1], alo[i][2], alo[i][3], ra + HALFB);
            }
            uint32_t bhi[8][2], blo[8][2];
#pragma unroll
            for (int jp = 0; jp < 4; ++jp) {
                uint32_t rb = bAddrBase + (uint32_t)jp * 16 * ROWB + (uint32_t)ks * 32;
                uint32_t r0, r1, r2, r3;
                LDM4(r0, r1, r2, r3, rb);
                bhi[2 * jp][0] = r0; bhi[2 * jp][1] = r1;
                bhi[2 * jp + 1][0] = r2; bhi[2 * jp + 1][1] = r3;
                LDM4(r0, r1, r2, r3, rb + HALFB);
                blo[2 * jp][0] = r0; blo[2 * jp][1] = r1;
                blo[2 * jp + 1][0] = r2; blo[2 * jp + 1][1] = r3;
            }
#pragma unroll
            for (int i = 0; i < 2; ++i)
#pragma unroll
                for (int j = 0; j < 8; ++j) {
                    MMA16816(acc[i][j], ahi[i], bhi[j]);
                    MMA16816(acc[i][j], ahi[i], blo[j]);
                    MMA16816(acc[i][j], alo[i], bhi[j]);
                }
        }

        // ---- epilogue ----
        float* C = (m == 0) ? c0 : ((m == 1) ? c1 : c2);
#pragma unroll
        for (int i = 0; i < 2; ++i) {
            int rA = row0 + wr0 + i * 16 + (lane >> 2);
            int rB = rA + 8;
#pragma unroll
            for (int j = 0; j < 8; ++j) {
                int c = wc0 + j * 8 + (lane & 3) * 2;
                if (c >= nout) continue;
                float b0 = bias[m * 128 + c];
                float b1 = bias[m * 128 + c + 1];
                if (rA < nrows) {
                    float o0 = acc[i][j][0] + b0;
                    float o1 = acc[i][j][1] + b1;
                    if (MODE == 1) { o0 = fmaxf(o0, 0.f); o1 = fmaxf(o1, 0.f); }
                    if (MODE == 3) {
                        const float* xo = xold + (size_t)rA * 128 + c;
                        o0 = alpha * o0 + (1.f - alpha) * xo[0];
                        o1 = alpha * o1 + (1.f - alpha) * xo[1];
                    }
                    *reinterpret_cast<float2*>(C + (size_t)rA * nout + c) = make_float2(o0, o1);
                }
                if (rB < nrows) {
                    float o0 = acc[i][j][2] + b0;
                    float o1 = acc[i][j][3] + b1;
                    if (MODE == 1) { o0 = fmaxf(o0, 0.f); o1 = fmaxf(o1, 0.f); }
                    if (MODE == 3) {
                        const float* xo = xold + (size_t)rB * 128 + c;
                        o0 = alpha * o0 + (1.f - alpha) * xo[0];
                        o1 = alpha * o1 + (1.f - alpha) * xo[1];
                    }
                    *reinterpret_cast<float2*>(C + (size_t)rB * nout + c) = make_float2(o0, o1);
                }
            }
        }
    }
}

// ---------------- edge kernels ----------------
__global__ void init_ms_kernel(int n)
{
    int i = blockIdx.x * blockDim.x + threadIdx.x;
    if (i < n) {
        g_m[0][i] = 0x007FFFFFu;  // fenc(-inf)
        g_m[1][i] = 0x007FFFFFu;
        g_s[0][i] = 0.f;
        g_s[1][i] = 0.f;
    }
}

__global__ void edge_score_kernel(const int* __restrict__ src, const int* __restrict__ dst,
                                  const float* __restrict__ q, const float* __restrict__ kr,
                                  float* __restrict__ sc, unsigned* __restrict__ mmax, int E)
{
    int idx = blockIdx.x * blockDim.x + threadIdx.x;
    if (idx >= E * NH) return;
    int e = idx >> 3, h = idx & 7;
    int si = src[e], di = dst[e];
    const float4* qp = reinterpret_cast<const float4*>(q + (size_t)di * HIDC + h * HD);
    const float4* kp = reinterpret_cast<const float4*>(kr + (size_t)si * HIDC + h * HD);
    float s = 0.f;
#pragma unroll
    for (int t = 0; t < 4; ++t) {
        float4 a = qp[t], b = kp[t];
        s += a.x * b.x + a.y * b.y + a.z * b.z + a.w * b.w;
    }
    // p_rel * 1/sqrt(D) already folded into q projection weights
    sc[idx] = s;
    atomicMax(&mmax[(size_t)di * NH + h], fenc(s));
}

__global__ void edge_exp_kernel(const int* __restrict__ dst, float* __restrict__ sc,
                                const unsigned* __restrict__ mmax, float* __restrict__ ssum, int E)
{
    int idx = blockIdx.x * blockDim.x + threadIdx.x;
    if (idx >= E * NH) return;
    int e = idx >> 3, h = idx & 7;
    int di = dst[e];
    float m = fdec(mmax[(size_t)di * NH + h]);
    float ex = __expf(sc[idx] - m);
    sc[idx] = ex;
    atomicAdd(&ssum[(size_t)di * NH + h], ex);
}

__global__ void edge_scatter_kernel(const int* __restrict__ src, const int* __restrict__ dst,
                                    const float* __restrict__ vr, const float* __restrict__ sc,
                                    const float* __restrict__ ssum, float* __restrict__ out, int E)
{
    int idx = blockIdx.x * blockDim.x + threadIdx.x;
    if (idx >= E * NH) return;
    int e = idx >> 3, h = idx & 7;
    int si = src[e], di = dst[e];
    float a = sc[idx] / (ssum[(size_t)di * NH + h] + 1e-16f);
    const float4* vp = reinterpret_cast<const float4*>(vr + (size_t)si * HIDC + h * HD);
    float* op = out + (size_t)di * HIDC + h * HD;
#pragma unroll
    for (int t = 0; t < 4; ++t) {
        float4 v = vp[t];
        asm volatile("red.global.add.v4.f32 [%0], {%1, %2, %3, %4};"
                     :: "l"(op + t * 4), "f"(v.x * a), "f"(v.y * a), "f"(v.z * a), "f"(v.w * a)
                     : "memory");
    }
}

// ---------------- launch ----------------
extern "C" void kernel_launch(void* const* d_in, const int* in_sizes, int n_in,
                              void* d_out, int out_size)
{
    const float* x_cpd    = (const float*)d_in[0];
    const float* x_ko     = (const float*)d_in[1];
    const int*   e_c2k    = (const int*)d_in[2];
    const int*   e_k2c    = (const int*)d_in[3];
    const float* w_in_cpd = (const float*)d_in[4];
    const float* b_in_cpd = (const float*)d_in[5];
    const float* w_in_ko  = (const float*)d_in[6];
    const float* b_in_ko  = (const float*)d_in[7];

    const float *w_k, *b_k, *w_q, *b_q, *w_v, *b_v;
    const float *a_rel, *m_rel, *p_rel, *w_a, *b_a, *skip, *w_out, *b_out;
    if (in_sizes[9] == 2 * 2 * HIDC) {
        w_k = (const float*)d_in[8];   b_k = (const float*)d_in[9];
        w_q = (const float*)d_in[10];  b_q = (const float*)d_in[11];
        w_v = (const float*)d_in[12];  b_v = (const float*)d_in[13];
        a_rel = (const float*)d_in[14]; m_rel = (const float*)d_in[15];
        p_rel = (const float*)d_in[16];
        w_a = (const float*)d_in[17];  b_a = (const float*)d_in[18];
        skip = (const float*)d_in[19];
        w_out = (const float*)d_in[20]; b_out = (const float*)d_in[21];
    } else {
        w_k = (const float*)d_in[8];   w_q = (const float*)d_in[9];
        w_v = (const float*)d_in[10];  w_a = (const float*)d_in[11];
        b_k = (const float*)d_in[12];  b_q = (const float*)d_in[13];
        b_v = (const float*)d_in[14];  b_a = (const float*)d_in[15];
        a_rel = (const float*)d_in[16]; m_rel = (const float*)d_in[17];
        p_rel = (const float*)d_in[18]; skip = (const float*)d_in[19];
        w_out = (const float*)d_in[20]; b_out = (const float*)d_in[21];
    }

    const int N = in_sizes[0] / 64;
    const int E = in_sizes[2] / 2;

    void* p;
    float *xA, *xB, *qb, *kr, *vr, *att, *sb, *sc;
    unsigned* mb;
    uint4* wblob;
    float* biasP;
    cudaGetSymbolAddress(&p, g_xA);  xA  = (float*)p;
    cudaGetSymbolAddress(&p, g_xB);  xB  = (float*)p;
    cudaGetSymbolAddress(&p, g_qb);  qb  = (float*)p;
    cudaGetSymbolAddress(&p, g_kr);  kr  = (float*)p;
    cudaGetSymbolAddress(&p, g_vr);  vr  = (float*)p;
    cudaGetSymbolAddress(&p, g_att); att = (float*)p;
    cudaGetSymbolAddress(&p, g_m);   mb  = (unsigned*)p;
    cudaGetSymbolAddress(&p, g_s);   sb  = (float*)p;
    cudaGetSymbolAddress(&p, g_sc);  sc  = (float*)p;
    cudaGetSymbolAddress(&p, g_wblob); wblob = (uint4*)p;
    cudaGetSymbolAddress(&p, g_biasP); biasP = (float*)p;

    const size_t NSTR = (size_t)NMAX * HIDC;
    const size_t MSTR = (size_t)NMAX * NH;
    const size_t ESTR = (size_t)EMAX * NH;

    // ---- weight prep jobs ----
    PrepArgs pa;
    auto setjob = [&](int idx, const float* W, const float* b, const float* rel,
                      const float* psc, int kin, int nout) {
        pa.j[idx].W = W; pa.j[idx].b = b; pa.j[idx].rel = rel; pa.j[idx].psc = psc;
        pa.j[idx].kin = kin; pa.j[idx].nout = nout;
        pa.j[idx].blob = wblob + (size_t)idx * 4352;
        pa.j[idx].bias = biasP + (size_t)idx * 128;
    };
    setjob(0, w_in_cpd, b_in_cpd, nullptr, nullptr, 64, 128);
    setjob(1, w_in_ko,  b_in_ko,  nullptr, nullptr, 128, 128);
    for (int l = 0; l < 2; ++l)
        for (int t = 0; t < 2; ++t) {
            int lt = l * 2 + t;
            int base = 2 + lt * 4;
            // q of type t is destination of relation r=1-t: fold p_rel[l,1-t] * 0.25
            setjob(base + 0, w_q + (size_t)lt * HIDC * HIDC, b_q + (size_t)lt * HIDC,
                   nullptr, p_rel + (size_t)(l * 2 + (1 - t)) * NH, 128, 128);
            // k of type t is source of relation r=t: compose a_rel[l,t]
            setjob(base + 1, w_k + (size_t)lt * HIDC * HIDC, b_k + (size_t)lt * HIDC,
                   a_rel + (size_t)lt * NH * HD * HD, nullptr, 128, 128);
            setjob(base + 2, w_v + (size_t)lt * HIDC * HIDC, b_v + (size_t)lt * HIDC,
                   m_rel + (size_t)lt * NH * HD * HD, nullptr, 128, 128);
            setjob(base + 3, w_a + (size_t)lt * HIDC * HIDC, b_a + (size_t)lt * HIDC,
                   nullptr, nullptr, 128, 128);
        }
    setjob(18, w_out, b_out, nullptr, nullptr, 128, 64);

    cudaFuncSetAttribute(gemm_hmma<0>, cudaFuncAttributeMaxDynamicSharedMemorySize, SMEM_TOT);
    cudaFuncSetAttribute(gemm_hmma<1>, cudaFuncAttributeMaxDynamicSharedMemorySize, SMEM_TOT);
    cudaFuncSetAttribute(gemm_hmma<3>, cudaFuncAttributeMaxDynamicSharedMemorySize, SMEM_TOT);

    prep_kernel<<<19, 256>>>(pa);

    const int gB = (N + 127) / 128;
    const int egrid = (E * NH + 255) / 256;
    const int igrid = (N * NH + 255) / 256;

    // input projections + relu
    gemm_hmma<1><<<gB, 256, SMEM_TOT>>>(x_cpd, 64, wblob + 0 * 4352, biasP + 0 * 128, 1, 128,
                                        xA + 0 * NSTR, nullptr, nullptr, N, nullptr, nullptr);
    gemm_hmma<1><<<gB, 256, SMEM_TOT>>>(x_ko, 128, wblob + 1 * 4352, biasP + 1 * 128, 1, 128,
                                        xA + 1 * NSTR, nullptr, nullptr, N, nullptr, nullptr);

    float* xcur = xA;
    float* xnxt = xB;

    for (int l = 0; l < 2; ++l) {
        for (int t = 0; t < 2; ++t) {
            int base = 2 + (l * 2 + t) * 4;
            // fused q/k/v (a_rel, m_rel, p_rel already composed into weights)
            gemm_hmma<0><<<gB, 256, SMEM_TOT>>>(xcur + t * NSTR, 128,
                                                wblob + (size_t)base * 4352, biasP + (size_t)base * 128,
                                                3, 128,
                                                qb + t * NSTR, kr + t * NSTR, vr + t * NSTR,
                                                N, nullptr, nullptr);
        }
        init_ms_kernel<<<igrid, 256>>>(N * NH);
        cudaMemsetAsync(att, 0, sizeof(float) * 2 * NSTR);
        for (int r = 0; r < 2; ++r) {
            const int* ep = (r == 0) ? e_c2k : e_k2c;
            int st = r, dt = 1 - r;
            edge_score_kernel<<<egrid, 256>>>(ep, ep + E, qb + dt * NSTR, kr + st * NSTR,
                                              sc + r * ESTR, mb + r * MSTR, E);
            edge_exp_kernel<<<egrid, 256>>>(ep + E, sc + r * ESTR, mb + r * MSTR, sb + r * MSTR, E);
            edge_scatter_kernel<<<egrid, 256>>>(ep, ep + E, vr + st * NSTR, sc + r * ESTR,
                                                sb + r * MSTR, att + dt * NSTR, E);
        }
        for (int t = 0; t < 2; ++t) {
            int base = 2 + (l * 2 + t) * 4 + 3;
            // x_new = sigmoid(skip)*(gelu(att)@w_a + b_a) + (1-sigmoid(skip))*x
            gemm_hmma<3><<<gB, 256, SMEM_TOT>>>(att + t * NSTR, 128,
                                                wblob + (size_t)base * 4352, biasP + (size_t)base * 128,
                                                1, 128,
                                                xnxt + t * NSTR, nullptr, nullptr,
                                                N, xcur + t * NSTR, skip + (l * 2 + t));
        }
        float* tmp = xcur; xcur = xnxt; xnxt = tmp;
    }

    float* out = (float*)d_out;
    gemm_hmma<0><<<gB, 256, SMEM_TOT>>>(xcur + 0 * NSTR, 128, wblob + 18 * 4352, biasP + 18 * 128,
                                        1, 64, out, nullptr, nullptr, N, nullptr, nullptr);
    gemm_hmma<0><<<gB, 256, SMEM_TOT>>>(xcur + 1 * NSTR, 128, wblob + 18 * 4352, biasP + 18 * 128,
                                        1, 64, out + (size_t)N * 64, nullptr, nullptr, N, nullptr, nullptr);
}

// round 4
// speedup vs baseline: 2.1353x; 1.1571x over previous
#include <cuda_runtime.h>
#include <cuda_bf16.h>
#include <math.h>
#include <stdint.h>

#define NMAX 200000
#define EMAX 600000
#define HIDC 128
#define NH 8
#define HD 16

// A/B smem tile: 128 rows x 136 bf16 (272 bytes per row; +16B pad -> conflict-free ldmatrix)
#define ROWB 272
#define HALFB 34816        // 128 * 272
#define SM_AH 0
#define SM_AL 34816
#define SM_BH 69632
#define SMEM_TOT 139264

// ---------------- scratch (device globals; no runtime allocation) ----------------
__device__ float g_xA[2][(size_t)NMAX * HIDC];
__device__ float g_xB[2][(size_t)NMAX * HIDC];
__device__ float g_qb[2][(size_t)NMAX * HIDC];
__device__ float g_kr[2][(size_t)NMAX * HIDC];
__device__ float g_vr[2][(size_t)NMAX * HIDC];
__device__ float g_att[2][(size_t)NMAX * HIDC];
__device__ float g_mf[2][(size_t)NMAX * NH];
__device__ float g_is[2][(size_t)NMAX * NH];
__device__ float g_sc[2][(size_t)EMAX * NH];
// CSR (built once per launch; edges constant across layers)
__device__ int g_deg[2][NMAX];
__device__ int g_off[2][NMAX + 1];
__device__ int g_cur[2][NMAX];
__device__ int g_csrc[2][EMAX];
// prepped weights: 19 matrices, each 69632 B (hi image 34816 + lo image 34816), smem-ready
__device__ uint4 g_wblob[19][4352];
__device__ float g_biasP[19][128];

// ---------------- helpers ----------------
__device__ __forceinline__ uint32_t smem_u32(const void* p) {
    uint32_t a;
    asm("{ .reg .u64 t; cvta.to.shared.u64 t, %1; cvt.u32.u64 %0, t; }" : "=r"(a) : "l"(p));
    return a;
}

#define LDM4(r0, r1, r2, r3, addr) \
    asm volatile("ldmatrix.sync.aligned.m8n8.x4.shared.b16 {%0,%1,%2,%3}, [%4];" \
                 : "=r"(r0), "=r"(r1), "=r"(r2), "=r"(r3) : "r"(addr))

#define MMA16816(c, a, b) \
    asm volatile("mma.sync.aligned.m16n8k16.row.col.f32.bf16.bf16.f32 " \
                 "{%0,%1,%2,%3},{%4,%5,%6,%7},{%8,%9},{%0,%1,%2,%3};" \
                 : "+f"((c)[0]), "+f"((c)[1]), "+f"((c)[2]), "+f"((c)[3]) \
                 : "r"((a)[0]), "r"((a)[1]), "r"((a)[2]), "r"((a)[3]), \
                   "r"((b)[0]), "r"((b)[1]))

__device__ __forceinline__ float gelu_f(float x) {
    return 0.5f * x * (1.0f + erff(x * 0.7071067811865475f));
}

// ---------------- weight prep: compose rel/p-scale, transpose to [n][k], bf16 hi/lo split ----------------
struct PrepJob {
    const float* W;    // [kin x nout] row-major
    const float* b;    // [nout]
    const float* rel;  // [8,16,16] or null
    const float* psc;  // [8] or null (also multiplies 0.25 = 1/sqrt(D))
    int kin;
    int nout;
    uint4* blob;
    float* bias;
};
struct PrepArgs { PrepJob j[19]; };

__global__ void prep_kernel(PrepArgs pa) {
    __shared__ float rel_s[2048];
    __shared__ float bsrc[128];
    const PrepJob jb = pa.j[blockIdx.x];
    const int tid = threadIdx.x;
    const bool hasrel = (jb.rel != nullptr);
    if (hasrel)
        for (int i = tid; i < 2048; i += 256) rel_s[i] = jb.rel[i];
    for (int i = tid; i < 128; i += 256) bsrc[i] = (i < jb.nout) ? jb.b[i] : 0.f;
    __syncthreads();

    char* blob = (char*)jb.blob;
    for (int i = tid; i < 16384; i += 256) {
        int k = i >> 7;
        int n = i & 127;
        float v = 0.f;
        if (k < jb.kin && n < jb.nout) {
            if (hasrel) {
                int h = n >> 4, e = n & 15;
                const float* wrow = jb.W + (size_t)k * 128 + h * 16;
                const float* rr = rel_s + h * 256 + e;
                float s = 0.f;
#pragma unroll
                for (int d = 0; d < 16; ++d) s = fmaf(wrow[d], rr[d * 16], s);
                v = s;
            } else {
                v = jb.W[(size_t)k * jb.nout + n];
            }
            if (jb.psc) v *= jb.psc[n >> 4] * 0.25f;
        }
        __nv_bfloat16 hi = __float2bfloat16(v);
        __nv_bfloat16 lo = __float2bfloat16(v - __bfloat162float(hi));
        uint32_t off = (uint32_t)n * ROWB + (uint32_t)k * 2;  // B stored [n][k]
        *reinterpret_cast<__nv_bfloat16*>(blob + off) = hi;
        *reinterpret_cast<__nv_bfloat16*>(blob + HALFB + off) = lo;
    }
    if (tid < 128) {
        int n = tid;
        float bc;
        if (hasrel) {
            int h = n >> 4, e = n & 15;
            float s = 0.f;
#pragma unroll
            for (int d = 0; d < 16; ++d) s = fmaf(bsrc[h * 16 + d], rel_s[h * 256 + d * 16 + e], s);
            bc = s;
        } else {
            bc = bsrc[n];
        }
        if (jb.psc) bc *= jb.psc[n >> 4] * 0.25f;
        jb.bias[n] = bc;
    }
}

// ---------------- bf16x3 HMMA GEMM (512 threads, 16 warps of 32x32 tiles) ----------------
// C[m] = epilogue( act_in(A[nrows x kin]) @ Wt[m] + bias[m] ), m = 0..nmat-1
// MODE: 0 plain, 1 relu, 3 pre-gelu on A + sigmoid-skip blend with xold
template <int MODE>
__global__ void __launch_bounds__(512, 1)
gemm_hmma(const float* __restrict__ A, int kin,
          const uint4* __restrict__ blob, const float* __restrict__ bias,
          int nmat, int nout,
          float* __restrict__ c0, float* __restrict__ c1, float* __restrict__ c2,
          int nrows, const float* __restrict__ xold, const float* __restrict__ skipp)
{
    extern __shared__ char smem[];
    const uint32_t sb = smem_u32(smem);
    const int tid = threadIdx.x;
    const int lane = tid & 31, wid = tid >> 5;
    const int wr0 = (wid & 3) * 32;   // warp row offset within 128
    const int wc0 = (wid >> 2) * 32;  // warp col offset within 128
    const int row0 = blockIdx.x * 128;

    // ---- load A tile 128 x 128 fp32 -> bf16 hi/lo into smem ----
#pragma unroll
    for (int it = 0; it < 4; ++it) {
        int gid = it * 512 + tid;
        int r = gid >> 4;
        int c8 = (gid & 15) * 8;
        float f[8];
        int grow = row0 + r;
        if (grow < nrows && c8 < kin) {
            const float4* p = reinterpret_cast<const float4*>(A + (size_t)grow * kin + c8);
            float4 v0 = p[0], v1 = p[1];
            f[0] = v0.x; f[1] = v0.y; f[2] = v0.z; f[3] = v0.w;
            f[4] = v1.x; f[5] = v1.y; f[6] = v1.z; f[7] = v1.w;
        } else {
#pragma unroll
            for (int j = 0; j < 8; ++j) f[j] = 0.f;
        }
        if (MODE == 3) {
#pragma unroll
            for (int j = 0; j < 8; ++j) f[j] = gelu_f(f[j]);
        }
        uint32_t hw[4], lw[4];
#pragma unroll
        for (int j = 0; j < 4; ++j) {
            __nv_bfloat16 h0 = __float2bfloat16(f[2 * j]);
            __nv_bfloat16 h1 = __float2bfloat16(f[2 * j + 1]);
            __nv_bfloat16 l0 = __float2bfloat16(f[2 * j] - __bfloat162float(h0));
            __nv_bfloat16 l1 = __float2bfloat16(f[2 * j + 1] - __bfloat162float(h1));
            hw[j] = (uint32_t)__bfloat16_as_ushort(h0) | ((uint32_t)__bfloat16_as_ushort(h1) << 16);
            lw[j] = (uint32_t)__bfloat16_as_ushort(l0) | ((uint32_t)__bfloat16_as_ushort(l1) << 16);
        }
        uint32_t off = (uint32_t)r * ROWB + (uint32_t)c8 * 2;
        *reinterpret_cast<uint4*>(smem + SM_AH + off) = make_uint4(hw[0], hw[1], hw[2], hw[3]);
        *reinterpret_cast<uint4*>(smem + SM_AL + off) = make_uint4(lw[0], lw[1], lw[2], lw[3]);
    }
    __syncthreads();

    float alpha = 0.f;
    if (MODE == 3) alpha = 1.f / (1.f + __expf(-skipp[0]));

    // fragment addresses (lane-dependent, k-step added in loop)
    const uint32_t aAddrBase = sb + SM_AH + (uint32_t)(wr0 + (lane & 15)) * ROWB + (uint32_t)(lane >> 4) * 16;
    const uint32_t bRowN = (uint32_t)(wc0 + (lane & 7) + ((lane >> 4) & 1) * 8);
    const uint32_t bColK = (uint32_t)(((lane >> 3) & 1) * 8);
    const uint32_t bAddrBase = sb + SM_BH + bRowN * ROWB + bColK * 2;

    for (int m = 0; m < nmat; ++m) {
        if (m) __syncthreads();
        // copy prepped B images (hi 34816 + lo 34816, contiguous)
        const uint4* src = blob + (size_t)m * 4352;
        for (int i = tid; i < 4352; i += 512)
            *reinterpret_cast<uint4*>(smem + SM_BH + i * 16) = src[i];
        __syncthreads();

        float acc[2][4][4];
#pragma unroll
        for (int i = 0; i < 2; ++i)
#pragma unroll
            for (int j = 0; j < 4; ++j)
#pragma unroll
                for (int t = 0; t < 4; ++t) acc[i][j][t] = 0.f;

#pragma unroll 1
        for (int ks = 0; ks < 8; ++ks) {
            uint32_t ahi[2][4], alo[2][4];
#pragma unroll
            for (int i = 0; i < 2; ++i) {
                uint32_t ra = aAddrBase + (uint32_t)i * 16 * ROWB + (uint32_t)ks * 32;
                LDM4(ahi[i][0], ahi[i][1], ahi[i][2], ahi[i][3], ra);
                LDM4(alo[i][0], alo[i][1], alo[i][2], alo[i][3], ra + HALFB);
            }
            uint32_t bhi[4][2], blo[4][2];
#pragma unroll
            for (int jp = 0; jp < 2; ++jp) {
                uint32_t rb = bAddrBase + (uint32_t)jp * 16 * ROWB + (uint32_t)ks * 32;
                uint32_t r0, r1, r2, r3;
                LDM4(r0, r1, r2, r3, rb);
                bhi[2 * jp][0] = r0; bhi[2 * jp][1] = r1;
                bhi[2 * jp + 1][0] = r2; bhi[2 * jp + 1][1] = r3;
                LDM4(r0, r1, r2, r3, rb + HALFB);
                blo[2 * jp][0] = r0; blo[2 * jp][1] = r1;
                blo[2 * jp + 1][0] = r2; blo[2 * jp + 1][1] = r3;
            }
#pragma unroll
            for (int i = 0; i < 2; ++i)
#pragma unroll
                for (int j = 0; j < 4; ++j) {
                    MMA16816(acc[i][j], ahi[i], bhi[j]);
                    MMA16816(acc[i][j], ahi[i], blo[j]);
                    MMA16816(acc[i][j], alo[i], bhi[j]);
                }
        }

        // ---- epilogue ----
        float* C = (m == 0) ? c0 : ((m == 1) ? c1 : c2);
#pragma unroll
        for (int i = 0; i < 2; ++i) {
            int rA = row0 + wr0 + i * 16 + (lane >> 2);
            int rB = rA + 8;
#pragma unroll
            for (int j = 0; j < 4; ++j) {
                int c = wc0 + j * 8 + (lane & 3) * 2;
                if (c >= nout) continue;
                float b0 = bias[m * 128 + c];
                float b1 = bias[m * 128 + c + 1];
                if (rA < nrows) {
                    float o0 = acc[i][j][0] + b0;
                    float o1 = acc[i][j][1] + b1;
                    if (MODE == 1) { o0 = fmaxf(o0, 0.f); o1 = fmaxf(o1, 0.f); }
                    if (MODE == 3) {
                        const float* xo = xold + (size_t)rA * 128 + c;
                        o0 = alpha * o0 + (1.f - alpha) * xo[0];
                        o1 = alpha * o1 + (1.f - alpha) * xo[1];
                    }
                    *reinterpret_cast<float2*>(C + (size_t)rA * nout + c) = make_float2(o0, o1);
                }
                if (rB < nrows) {
                    float o0 = acc[i][j][2] + b0;
                    float o1 = acc[i][j][3] + b1;
                    if (MODE == 1) { o0 = fmaxf(o0, 0.f); o1 = fmaxf(o1, 0.f); }
                    if (MODE == 3) {
                        const float* xo = xold + (size_t)rB * 128 + c;
                        o0 = alpha * o0 + (1.f - alpha) * xo[0];
                        o1 = alpha * o1 + (1.f - alpha) * xo[1];
                    }
                    *reinterpret_cast<float2*>(C + (size_t)rB * nout + c) = make_float2(o0, o1);
                }
            }
        }
    }
}

// ---------------- CSR build ----------------
__global__ void hist_kernel(const int* __restrict__ dst, int* __restrict__ deg, int E)
{
    int i = blockIdx.x * blockDim.x + threadIdx.x;
    if (i < E) atomicAdd(&deg[dst[i]], 1);
}

__global__ void scan_kernel(const int* __restrict__ deg, int* __restrict__ off, int n)
{
    __shared__ int wsum[32];
    __shared__ int carry;
    const int tid = threadIdx.x;  // 1024
    if (tid == 0) carry = 0;
    __syncthreads();
    for (int base = 0; base < n; base += 1024) {
        int v = (base + tid < n) ? deg[base + tid] : 0;
        int x = v;
#pragma unroll
        for (int d = 1; d < 32; d <<= 1) {
            int y = __shfl_up_sync(0xffffffffu, x, d);
            if ((tid & 31) >= d) x += y;
        }
        if ((tid & 31) == 31) wsum[tid >> 5] = x;
        __syncthreads();
        if (tid < 32) {
            int w = wsum[tid];
#pragma unroll
            for (int d = 1; d < 32; d <<= 1) {
                int y = __shfl_up_sync(0xffffffffu, w, d);
                if (tid >= d) w += y;
            }
            wsum[tid] = w;
        }
        __syncthreads();
        int incl = x + ((tid >= 32) ? wsum[(tid >> 5) - 1] : 0) + carry;
        if (base + tid < n) off[base + tid + 1] = incl;
        __syncthreads();
        if (tid == 1023) carry = incl;
        __syncthreads();
    }
    if (tid == 0) off[0] = 0;
}

__global__ void fill_kernel(const int* __restrict__ src, const int* __restrict__ dst,
                            int* __restrict__ cur, int* __restrict__ csrc, int E)
{
    int i = blockIdx.x * blockDim.x + threadIdx.x;
    if (i < E) {
        int p = atomicAdd(&cur[dst[i]], 1);
        csrc[p] = src[i];
    }
}

// ---------------- edge kernels: warp per dst node, online softmax, no atomics ----------------
__global__ void attn_score(const int* __restrict__ off, const int* __restrict__ csrc,
                           const float* __restrict__ q, const float* __restrict__ kr,
                           float* __restrict__ sc, float* __restrict__ mo,
                           float* __restrict__ iso, int n)
{
    int w = (blockIdx.x * blockDim.x + threadIdx.x) >> 5;
    int lane = threadIdx.x & 31;
    if (w >= n) return;
    int beg = off[w], end = off[w + 1];
    float4 q4 = *reinterpret_cast<const float4*>(q + (size_t)w * HIDC + lane * 4);
    float m = -INFINITY, ss = 0.f;
    const int h = lane >> 2, part = lane & 3;
    for (int i = beg; i < end; ++i) {
        int s = csrc[i];
        float4 k4 = *reinterpret_cast<const float4*>(kr + (size_t)s * HIDC + lane * 4);
        float p = q4.x * k4.x + q4.y * k4.y + q4.z * k4.z + q4.w * k4.w;
        p += __shfl_xor_sync(0xffffffffu, p, 1);
        p += __shfl_xor_sync(0xffffffffu, p, 2);
        if (part == 0) sc[(size_t)i * NH + h] = p;
        float mn = fmaxf(m, p);
        ss = ss * __expf(m - mn) + __expf(p - mn);
        m = mn;
    }
    if (part == 0) {
        if (!isfinite(m)) m = 0.f;
        mo[(size_t)w * NH + h] = m;
        iso[(size_t)w * NH + h] = 1.f / (ss + 1e-16f);
    }
}

__global__ void attn_out(const int* __restrict__ off, const int* __restrict__ csrc,
                         const float* __restrict__ vr, const float* __restrict__ sc,
                         const float* __restrict__ mo, const float* __restrict__ iso,
                         float* __restrict__ out, int n)
{
    int w = (blockIdx.x * blockDim.x + threadIdx.x) >> 5;
    int lane = threadIdx.x & 31;
    if (w >= n) return;
    int beg = off[w], end = off[w + 1];
    const int h = lane >> 2;
    float m = mo[(size_t)w * NH + h];
    float is = iso[(size_t)w * NH + h];
    float4 acc = make_float4(0.f, 0.f, 0.f, 0.f);
    for (int i = beg; i < end; ++i) {
        int s = csrc[i];
        float p = sc[(size_t)i * NH + h];
        float a = __expf(p - m) * is;
        float4 v = *reinterpret_cast<const float4*>(vr + (size_t)s * HIDC + lane * 4);
        acc.x += v.x * a; acc.y += v.y * a; acc.z += v.z * a; acc.w += v.w * a;
    }
    *reinterpret_cast<float4*>(out + (size_t)w * HIDC + lane * 4) = acc;
}

// ---------------- launch ----------------
extern "C" void kernel_launch(void* const* d_in, const int* in_sizes, int n_in,
                              void* d_out, int out_size)
{
    const float* x_cpd    = (const float*)d_in[0];
    const float* x_ko     = (const float*)d_in[1];
    const int*   e_c2k    = (const int*)d_in[2];
    const int*   e_k2c    = (const int*)d_in[3];
    const float* w_in_cpd = (const float*)d_in[4];
    const float* b_in_cpd = (const float*)d_in[5];
    const float* w_in_ko  = (const float*)d_in[6];
    const float* b_in_ko  = (const float*)d_in[7];

    const float *w_k, *b_k, *w_q, *b_q, *w_v, *b_v;
    const float *a_rel, *m_rel, *p_rel, *w_a, *b_a, *skip, *w_out, *b_out;
    if (in_sizes[9] == 2 * 2 * HIDC) {
        w_k = (const float*)d_in[8];   b_k = (const float*)d_in[9];
        w_q = (const float*)d_in[10];  b_q = (const float*)d_in[11];
        w_v = (const float*)d_in[12];  b_v = (const float*)d_in[13];
        a_rel = (const float*)d_in[14]; m_rel = (const float*)d_in[15];
        p_rel = (const float*)d_in[16];
        w_a = (const float*)d_in[17];  b_a = (const float*)d_in[18];
        skip = (const float*)d_in[19];
        w_out = (const float*)d_in[20]; b_out = (const float*)d_in[21];
    } else {
        w_k = (const float*)d_in[8];   w_q = (const float*)d_in[9];
        w_v = (const float*)d_in[10];  w_a = (const float*)d_in[11];
        b_k = (const float*)d_in[12];  b_q = (const float*)d_in[13];
        b_v = (const float*)d_in[14];  b_a = (const float*)d_in[15];
        a_rel = (const float*)d_in[16]; m_rel = (const float*)d_in[17];
        p_rel = (const float*)d_in[18]; skip = (const float*)d_in[19];
        w_out = (const float*)d_in[20]; b_out = (const float*)d_in[21];
    }

    const int N = in_sizes[0] / 64;
    const int E = in_sizes[2] / 2;

    void* p;
    float *xA, *xB, *qb, *kr, *vr, *att, *mf, *isv, *sc;
    int *deg, *off, *cur, *csrc;
    uint4* wblob;
    float* biasP;
    cudaGetSymbolAddress(&p, g_xA);  xA  = (float*)p;
    cudaGetSymbolAddress(&p, g_xB);  xB  = (float*)p;
    cudaGetSymbolAddress(&p, g_qb);  qb  = (float*)p;
    cudaGetSymbolAddress(&p, g_kr);  kr  = (float*)p;
    cudaGetSymbolAddress(&p, g_vr);  vr  = (float*)p;
    cudaGetSymbolAddress(&p, g_att); att = (float*)p;
    cudaGetSymbolAddress(&p, g_mf);  mf  = (float*)p;
    cudaGetSymbolAddress(&p, g_is);  isv = (float*)p;
    cudaGetSymbolAddress(&p, g_sc);  sc  = (float*)p;
    cudaGetSymbolAddress(&p, g_deg); deg = (int*)p;
    cudaGetSymbolAddress(&p, g_off); off = (int*)p;
    cudaGetSymbolAddress(&p, g_cur); cur = (int*)p;
    cudaGetSymbolAddress(&p, g_csrc); csrc = (int*)p;
    cudaGetSymbolAddress(&p, g_wblob); wblob = (uint4*)p;
    cudaGetSymbolAddress(&p, g_biasP); biasP = (float*)p;

    const size_t NSTR = (size_t)NMAX * HIDC;
    const size_t MSTR = (size_t)NMAX * NH;
    const size_t ESTR = (size_t)EMAX * NH;

    // ---- weight prep jobs ----
    PrepArgs pa;
    auto setjob = [&](int idx, const float* W, const float* b, const float* rel,
                      const float* psc, int kin, int nout) {
        pa.j[idx].W = W; pa.j[idx].b = b; pa.j[idx].rel = rel; pa.j[idx].psc = psc;
        pa.j[idx].kin = kin; pa.j[idx].nout = nout;
        pa.j[idx].blob = wblob + (size_t)idx * 4352;
        pa.j[idx].bias = biasP + (size_t)idx * 128;
    };
    setjob(0, w_in_cpd, b_in_cpd, nullptr, nullptr, 64, 128);
    setjob(1, w_in_ko,  b_in_ko,  nullptr, nullptr, 128, 128);
    for (int l = 0; l < 2; ++l)
        for (int t = 0; t < 2; ++t) {
            int lt = l * 2 + t;
            int base = 2 + lt * 4;
            // q of type t is destination of relation r=1-t: fold p_rel[l,1-t] * 0.25
            setjob(base + 0, w_q + (size_t)lt * HIDC * HIDC, b_q + (size_t)lt * HIDC,
                   nullptr, p_rel + (size_t)(l * 2 + (1 - t)) * NH, 128, 128);
            // k of type t is source of relation r=t: compose a_rel[l,t]
            setjob(base + 1, w_k + (size_t)lt * HIDC * HIDC, b_k + (size_t)lt * HIDC,
                   a_rel + (size_t)lt * NH * HD * HD, nullptr, 128, 128);
            setjob(base + 2, w_v + (size_t)lt * HIDC * HIDC, b_v + (size_t)lt * HIDC,
                   m_rel + (size_t)lt * NH * HD * HD, nullptr, 128, 128);
            setjob(base + 3, w_a + (size_t)lt * HIDC * HIDC, b_a + (size_t)lt * HIDC,
                   nullptr, nullptr, 128, 128);
        }
    setjob(18, w_out, b_out, nullptr, nullptr, 128, 64);

    cudaFuncSetAttribute(gemm_hmma<0>, cudaFuncAttributeMaxDynamicSharedMemorySize, SMEM_TOT);
    cudaFuncSetAttribute(gemm_hmma<1>, cudaFuncAttributeMaxDynamicSharedMemorySize, SMEM_TOT);
    cudaFuncSetAttribute(gemm_hmma<3>, cudaFuncAttributeMaxDynamicSharedMemorySize, SMEM_TOT);

    const int gB = (N + 127) / 128;
    const int egrid = (E + 255) / 256;
    const int wgrid = (N + 7) / 8;  // warp-per-node kernels, 256 threads

    // ---- CSR build (edges are layer-invariant; build once) ----
    cudaMemsetAsync(deg, 0, sizeof(int) * 2 * NMAX);
    for (int r = 0; r < 2; ++r) {
        const int* ep = (r == 0) ? e_c2k : e_k2c;
        hist_kernel<<<egrid, 256>>>(ep + E, deg + r * NMAX, E);
        scan_kernel<<<1, 1024>>>(deg + r * NMAX, off + r * (NMAX + 1), N);
        cudaMemcpyAsync(cur + r * NMAX, off + r * (NMAX + 1), sizeof(int) * N,
                        cudaMemcpyDeviceToDevice);
        fill_kernel<<<egrid, 256>>>(ep, ep + E, cur + r * NMAX, csrc + r * EMAX, E);
    }

    prep_kernel<<<19, 256>>>(pa);

    // input projections + relu
    gemm_hmma<1><<<gB, 512, SMEM_TOT>>>(x_cpd, 64, wblob + 0 * 4352, biasP + 0 * 128, 1, 128,
                                        xA + 0 * NSTR, nullptr, nullptr, N, nullptr, nullptr);
    gemm_hmma<1><<<gB, 512, SMEM_TOT>>>(x_ko, 128, wblob + 1 * 4352, biasP + 1 * 128, 1, 128,
                                        xA + 1 * NSTR, nullptr, nullptr, N, nullptr, nullptr);

    float* xcur = xA;
    float* xnxt = xB;

    for (int l = 0; l < 2; ++l) {
        for (int t = 0; t < 2; ++t) {
            int base = 2 + (l * 2 + t) * 4;
            // fused q/k/v (a_rel, m_rel, p_rel already composed into weights)
            gemm_hmma<0><<<gB, 512, SMEM_TOT>>>(xcur + t * NSTR, 128,
                                                wblob + (size_t)base * 4352, biasP + (size_t)base * 128,
                                                3, 128,
                                                qb + t * NSTR, kr + t * NSTR, vr + t * NSTR,
                                                N, nullptr, nullptr);
        }
        for (int r = 0; r < 2; ++r) {
            int st = r, dt = 1 - r;
            attn_score<<<wgrid, 256>>>(off + r * (NMAX + 1), csrc + r * EMAX,
                                       qb + dt * NSTR, kr + st * NSTR,
                                       sc + r * ESTR, mf + r * MSTR, isv + r * MSTR, N);
            attn_out<<<wgrid, 256>>>(off + r * (NMAX + 1), csrc + r * EMAX,
                                     vr + st * NSTR, sc + r * ESTR,
                                     mf + r * MSTR, isv + r * MSTR, att + dt * NSTR, N);
        }
        for (int t = 0; t < 2; ++t) {
            int base = 2 + (l * 2 + t) * 4 + 3;
            // x_new = sigmoid(skip)*(gelu(att)@w_a + b_a) + (1-sigmoid(skip))*x
            gemm_hmma<3><<<gB, 512, SMEM_TOT>>>(att + t * NSTR, 128,
                                                wblob + (size_t)base * 4352, biasP + (size_t)base * 128,
                                                1, 128,
                                                xnxt + t * NSTR, nullptr, nullptr,
                                                N, xcur + t * NSTR, skip + (l * 2 + t));
        }
        float* tmp = xcur; xcur = xnxt; xnxt = tmp;
    }

    // final output projection: x[0] and x[1] are contiguous in the ping-pong buffer
    float* out = (float*)d_out;
    const int gB2 = (2 * N + 127) / 128;
    gemm_hmma<0><<<gB2, 512, SMEM_TOT>>>(xcur, 128, wblob + 18 * 4352, biasP + 18 * 128,
                                         1, 64, out, nullptr, nullptr, 2 * N, nullptr, nullptr);
}